// round 2
// baseline (speedup 1.0000x reference)
#include <cuda_runtime.h>

#define BB 32
#define HH 480
#define WW 640
#define HW (HH*WW)          // 307200
#define HW4 (HW/4)          // 76800 float4 per plane
#define NQUAD (BB*HW4)      // 2,457,600 float4 pixel-quads
#define EPS 1e-5

#define RED_BLOCKS 1184
#define RED_THREADS 256

// 9 partial sums per block: s0,s1,s2, s00,s01,s02,s11,s12,s22
__device__ float g_partials[RED_BLOCKS * 9];
__device__ float g_A[8 * 3];
__device__ float g_c[8];

// ---------------------------------------------------------------------------
// Pass 1: deterministic moment reduction over x [32,3,H,W]
// ---------------------------------------------------------------------------
__global__ void reduce_kernel(const float4* __restrict__ X) {
    float s[9];
#pragma unroll
    for (int j = 0; j < 9; j++) s[j] = 0.f;

    const int stride = gridDim.x * blockDim.x;
    for (int idx = blockIdx.x * blockDim.x + threadIdx.x; idx < NQUAD; idx += stride) {
        int b = idx / HW4;
        int p = idx - b * HW4;
        const float4* base = X + b * 3 * HW4 + p;
        float4 x0 = base[0];
        float4 x1 = base[HW4];
        float4 x2 = base[2 * HW4];

        s[0] += x0.x + x0.y + x0.z + x0.w;
        s[1] += x1.x + x1.y + x1.z + x1.w;
        s[2] += x2.x + x2.y + x2.z + x2.w;
        s[3] += x0.x*x0.x + x0.y*x0.y + x0.z*x0.z + x0.w*x0.w;
        s[4] += x0.x*x1.x + x0.y*x1.y + x0.z*x1.z + x0.w*x1.w;
        s[5] += x0.x*x2.x + x0.y*x2.y + x0.z*x2.z + x0.w*x2.w;
        s[6] += x1.x*x1.x + x1.y*x1.y + x1.z*x1.z + x1.w*x1.w;
        s[7] += x1.x*x2.x + x1.y*x2.y + x1.z*x2.z + x1.w*x2.w;
        s[8] += x2.x*x2.x + x2.y*x2.y + x2.z*x2.z + x2.w*x2.w;
    }

    // warp tree reduce (deterministic)
#pragma unroll
    for (int j = 0; j < 9; j++)
#pragma unroll
        for (int off = 16; off > 0; off >>= 1)
            s[j] += __shfl_down_sync(0xffffffffu, s[j], off);

    __shared__ float sh[RED_THREADS / 32][9];
    int lane = threadIdx.x & 31;
    int warp = threadIdx.x >> 5;
    if (lane == 0) {
#pragma unroll
        for (int j = 0; j < 9; j++) sh[warp][j] = s[j];
    }
    __syncthreads();
    if (threadIdx.x == 0) {
        float t[9];
#pragma unroll
        for (int j = 0; j < 9; j++) t[j] = 0.f;
        for (int w = 0; w < RED_THREADS / 32; w++)
#pragma unroll
            for (int j = 0; j < 9; j++) t[j] += sh[w][j];
#pragma unroll
        for (int j = 0; j < 9; j++) g_partials[blockIdx.x * 9 + j] = t[j];
    }
}

// ---------------------------------------------------------------------------
// Pass 2: fold the whole network into A[8][3], c[8] (double precision)
// ---------------------------------------------------------------------------
__global__ void finalize_kernel(
    const float* __restrict__ w1, const float* __restrict__ b1,
    const float* __restrict__ g2, const float* __restrict__ be2,
    const float* __restrict__ w3, const float* __restrict__ b3,
    const float* __restrict__ w4, const float* __restrict__ b4,
    const float* __restrict__ g5, const float* __restrict__ be5,
    const float* __restrict__ w6, const float* __restrict__ b6,
    const float* __restrict__ w7, const float* __restrict__ b7,
    const float* __restrict__ w8, const float* __restrict__ b8)
{
    __shared__ double sums[9];
    int t = threadIdx.x;
    if (t < 9) {
        double acc = 0.0;
        for (int i = 0; i < RED_BLOCKS; i++) acc += (double)g_partials[i * 9 + t];
        sums[t] = acc;
    }
    __syncthreads();
    if (t != 0) return;

    const double N = (double)BB * (double)HW;
    double m[3];
    for (int k = 0; k < 3; k++) m[k] = sums[k] / N;
    double E[3][3];
    E[0][0] = sums[3] / N; E[0][1] = E[1][0] = sums[4] / N; E[0][2] = E[2][0] = sums[5] / N;
    E[1][1] = sums[6] / N; E[1][2] = E[2][1] = sums[7] / N; E[2][2] = sums[8] / N;
    double Cov[3][3];
    for (int k = 0; k < 3; k++)
        for (int d = 0; d < 3; d++)
            Cov[k][d] = E[k][d] - m[k] * m[d];

    double M[8][3], c[8], Mn[8][3], cn[8];
    // layer 1: conv1x1 (3x3)
    for (int r = 0; r < 3; r++) {
        for (int k = 0; k < 3; k++) M[r][k] = (double)w1[r * 3 + k];
        c[r] = (double)b1[r];
    }
    // layer 2: BN over v1 (rows=3)
    for (int r = 0; r < 3; r++) {
        double mean = c[r];
        for (int k = 0; k < 3; k++) mean += M[r][k] * m[k];
        double var = 0.0;
        for (int k = 0; k < 3; k++)
            for (int d = 0; d < 3; d++)
                var += M[r][k] * Cov[k][d] * M[r][d];
        double s = (double)g2[r] / sqrt(var + EPS);
        for (int k = 0; k < 3; k++) M[r][k] *= s;
        c[r] = s * (c[r] - mean) + (double)be2[r];
    }
    // layer 3: conv w3 [8,3]
    for (int o = 0; o < 8; o++) {
        for (int k = 0; k < 3; k++) {
            double a = 0.0;
            for (int r = 0; r < 3; r++) a += (double)w3[o * 3 + r] * M[r][k];
            Mn[o][k] = a;
        }
        double a = (double)b3[o];
        for (int r = 0; r < 3; r++) a += (double)w3[o * 3 + r] * c[r];
        cn[o] = a;
    }
    for (int o = 0; o < 8; o++) { for (int k = 0; k < 3; k++) M[o][k] = Mn[o][k]; c[o] = cn[o]; }
    // layer 4: conv w4 [8,8]
    for (int o = 0; o < 8; o++) {
        for (int k = 0; k < 3; k++) {
            double a = 0.0;
            for (int r = 0; r < 8; r++) a += (double)w4[o * 8 + r] * M[r][k];
            Mn[o][k] = a;
        }
        double a = (double)b4[o];
        for (int r = 0; r < 8; r++) a += (double)w4[o * 8 + r] * c[r];
        cn[o] = a;
    }
    for (int o = 0; o < 8; o++) { for (int k = 0; k < 3; k++) M[o][k] = Mn[o][k]; c[o] = cn[o]; }
    // layer 5: BN over v4 (rows=8)
    for (int o = 0; o < 8; o++) {
        double mean = c[o];
        for (int k = 0; k < 3; k++) mean += M[o][k] * m[k];
        double var = 0.0;
        for (int k = 0; k < 3; k++)
            for (int d = 0; d < 3; d++)
                var += M[o][k] * Cov[k][d] * M[o][d];
        double s = (double)g5[o] / sqrt(var + EPS);
        for (int k = 0; k < 3; k++) M[o][k] *= s;
        c[o] = s * (c[o] - mean) + (double)be5[o];
    }
    // layers 6,7,8: conv [8,8]
    const float* Ws[3] = { w6, w7, w8 };
    const float* Bs[3] = { b6, b7, b8 };
    for (int L = 0; L < 3; L++) {
        const float* Wl = Ws[L];
        const float* Bl = Bs[L];
        for (int o = 0; o < 8; o++) {
            for (int k = 0; k < 3; k++) {
                double a = 0.0;
                for (int r = 0; r < 8; r++) a += (double)Wl[o * 8 + r] * M[r][k];
                Mn[o][k] = a;
            }
            double a = (double)Bl[o];
            for (int r = 0; r < 8; r++) a += (double)Wl[o * 8 + r] * c[r];
            cn[o] = a;
        }
        for (int o = 0; o < 8; o++) { for (int k = 0; k < 3; k++) M[o][k] = Mn[o][k]; c[o] = cn[o]; }
    }

    for (int o = 0; o < 8; o++) {
        for (int k = 0; k < 3; k++) g_A[o * 3 + k] = (float)M[o][k];
        g_c[o] = (float)c[o];
    }
}

// ---------------------------------------------------------------------------
// Pass 3: out[b,o,h,w] = sum_k A[o][k] * x[b,k,h,w] + c[o]
// ---------------------------------------------------------------------------
__global__ void __launch_bounds__(256) apply_kernel(const float4* __restrict__ X,
                                                    float4* __restrict__ OUT) {
    int idx = blockIdx.x * blockDim.x + threadIdx.x;
    if (idx >= NQUAD) return;
    int b = idx / HW4;
    int p = idx - b * HW4;

    float a0[8], a1[8], a2[8], cc[8];
#pragma unroll
    for (int o = 0; o < 8; o++) {
        a0[o] = g_A[o * 3 + 0];
        a1[o] = g_A[o * 3 + 1];
        a2[o] = g_A[o * 3 + 2];
        cc[o] = g_c[o];
    }

    const float4* base = X + b * 3 * HW4 + p;
    float4 x0 = __ldg(base);
    float4 x1 = __ldg(base + HW4);
    float4 x2 = __ldg(base + 2 * HW4);

    float4* ob = OUT + b * 8 * HW4 + p;
#pragma unroll
    for (int o = 0; o < 8; o++) {
        float4 r;
        r.x = fmaf(a0[o], x0.x, fmaf(a1[o], x1.x, fmaf(a2[o], x2.x, cc[o])));
        r.y = fmaf(a0[o], x0.y, fmaf(a1[o], x1.y, fmaf(a2[o], x2.y, cc[o])));
        r.z = fmaf(a0[o], x0.z, fmaf(a1[o], x1.z, fmaf(a2[o], x2.z, cc[o])));
        r.w = fmaf(a0[o], x0.w, fmaf(a1[o], x1.w, fmaf(a2[o], x2.w, cc[o])));
        __stcs(ob + o * HW4, r);  // streaming store: don't thrash L2 (x may still be resident)
    }
}

extern "C" void kernel_launch(void* const* d_in, const int* in_sizes, int n_in,
                              void* d_out, int out_size) {
    const float* x1  = (const float*)d_in[0];
    const float* w1  = (const float*)d_in[1];
    const float* b1  = (const float*)d_in[2];
    const float* g2  = (const float*)d_in[3];
    const float* be2 = (const float*)d_in[4];
    const float* w3  = (const float*)d_in[5];
    const float* b3  = (const float*)d_in[6];
    const float* w4  = (const float*)d_in[7];
    const float* b4  = (const float*)d_in[8];
    const float* g5  = (const float*)d_in[9];
    const float* be5 = (const float*)d_in[10];
    const float* w6  = (const float*)d_in[11];
    const float* b6  = (const float*)d_in[12];
    const float* w7  = (const float*)d_in[13];
    const float* b7  = (const float*)d_in[14];
    const float* w8  = (const float*)d_in[15];
    const float* b8  = (const float*)d_in[16];

    reduce_kernel<<<RED_BLOCKS, RED_THREADS>>>((const float4*)x1);
    finalize_kernel<<<1, 32>>>(w1, b1, g2, be2, w3, b3, w4, b4,
                               g5, be5, w6, b6, w7, b7, w8, b8);
    apply_kernel<<<(NQUAD + 255) / 256, 256>>>((const float4*)x1, (float4*)d_out);
}

// round 4
// speedup vs baseline: 1.1841x; 1.1841x over previous
#include <cuda_runtime.h>

#define BB 32
#define HH 480
#define WW 640
#define HW (HH*WW)          // 307200
#define HW4 (HW/4)          // 76800 float4 per plane
#define EPS 1e-5

// reduce: grid (RED_GX, BB) x 256 threads
#define RED_GX 25
#define RED_THREADS 256
#define RED_BLOCKS (RED_GX * BB)   // 800

// apply: grid (APL_GX, BB) x 256 threads, 2 quads per thread
#define APL_GX 150                 // 150 * 512 = 76800 quads per batch

__device__ float g_partials[RED_BLOCKS * 9];
__device__ float g_A[8 * 3];
__device__ float g_c[8];

// ---------------------------------------------------------------------------
// Pass 1: moment reduction over x [32,3,H,W].  blockIdx.y = batch.
// ---------------------------------------------------------------------------
__global__ void __launch_bounds__(RED_THREADS) reduce_kernel(const float4* __restrict__ X) {
    float s[9];
#pragma unroll
    for (int j = 0; j < 9; j++) s[j] = 0.f;

    const int b = blockIdx.y;
    const float4* base = X + (size_t)b * 3 * HW4;

#pragma unroll 2
    for (int p = blockIdx.x * RED_THREADS + threadIdx.x; p < HW4; p += RED_GX * RED_THREADS) {
        float4 x0 = base[p];
        float4 x1 = base[p + HW4];
        float4 x2 = base[p + 2 * HW4];

        s[0] += x0.x + x0.y + x0.z + x0.w;
        s[1] += x1.x + x1.y + x1.z + x1.w;
        s[2] += x2.x + x2.y + x2.z + x2.w;
        s[3] += x0.x*x0.x + x0.y*x0.y + x0.z*x0.z + x0.w*x0.w;
        s[4] += x0.x*x1.x + x0.y*x1.y + x0.z*x1.z + x0.w*x1.w;
        s[5] += x0.x*x2.x + x0.y*x2.y + x0.z*x2.z + x0.w*x2.w;
        s[6] += x1.x*x1.x + x1.y*x1.y + x1.z*x1.z + x1.w*x1.w;
        s[7] += x1.x*x2.x + x1.y*x2.y + x1.z*x2.z + x1.w*x2.w;
        s[8] += x2.x*x2.x + x2.y*x2.y + x2.z*x2.z + x2.w*x2.w;
    }

#pragma unroll
    for (int j = 0; j < 9; j++)
#pragma unroll
        for (int off = 16; off > 0; off >>= 1)
            s[j] += __shfl_down_sync(0xffffffffu, s[j], off);

    __shared__ float sh[RED_THREADS / 32][9];
    int lane = threadIdx.x & 31;
    int warp = threadIdx.x >> 5;
    if (lane == 0) {
#pragma unroll
        for (int j = 0; j < 9; j++) sh[warp][j] = s[j];
    }
    __syncthreads();
    if (threadIdx.x == 0) {
        float t[9];
#pragma unroll
        for (int j = 0; j < 9; j++) t[j] = 0.f;
        for (int w = 0; w < RED_THREADS / 32; w++)
#pragma unroll
            for (int j = 0; j < 9; j++) t[j] += sh[w][j];
        int bid = blockIdx.y * RED_GX + blockIdx.x;
#pragma unroll
        for (int j = 0; j < 9; j++) g_partials[bid * 9 + j] = t[j];
    }
}

// ---------------------------------------------------------------------------
// Pass 2: parallel partial-sum (9 warps), then fold network into A, c.
// ---------------------------------------------------------------------------
__global__ void finalize_kernel(
    const float* __restrict__ w1, const float* __restrict__ b1,
    const float* __restrict__ g2, const float* __restrict__ be2,
    const float* __restrict__ w3, const float* __restrict__ b3,
    const float* __restrict__ w4, const float* __restrict__ b4,
    const float* __restrict__ g5, const float* __restrict__ be5,
    const float* __restrict__ w6, const float* __restrict__ b6,
    const float* __restrict__ w7, const float* __restrict__ b7,
    const float* __restrict__ w8, const float* __restrict__ b8)
{
    __shared__ double sums[9];
    int t = threadIdx.x;          // 288 threads = 9 warps
    int warp = t >> 5;
    int lane = t & 31;
    if (warp < 9) {
        double acc = 0.0;
        for (int i = lane; i < RED_BLOCKS; i += 32)
            acc += (double)g_partials[i * 9 + warp];
#pragma unroll
        for (int off = 16; off > 0; off >>= 1)
            acc += __shfl_down_sync(0xffffffffu, acc, off);
        if (lane == 0) sums[warp] = acc;
    }
    __syncthreads();
    if (t != 0) return;

    const double N = (double)BB * (double)HW;
    double m[3];
    for (int k = 0; k < 3; k++) m[k] = sums[k] / N;
    double E[3][3];
    E[0][0] = sums[3] / N; E[0][1] = E[1][0] = sums[4] / N; E[0][2] = E[2][0] = sums[5] / N;
    E[1][1] = sums[6] / N; E[1][2] = E[2][1] = sums[7] / N; E[2][2] = sums[8] / N;
    double Cov[3][3];
    for (int k = 0; k < 3; k++)
        for (int d = 0; d < 3; d++)
            Cov[k][d] = E[k][d] - m[k] * m[d];

    double M[8][3], c[8], Mn[8][3], cn[8];
    for (int r = 0; r < 3; r++) {
        for (int k = 0; k < 3; k++) M[r][k] = (double)w1[r * 3 + k];
        c[r] = (double)b1[r];
    }
    for (int r = 0; r < 3; r++) {               // BN2
        double mean = c[r];
        for (int k = 0; k < 3; k++) mean += M[r][k] * m[k];
        double var = 0.0;
        for (int k = 0; k < 3; k++)
            for (int d = 0; d < 3; d++)
                var += M[r][k] * Cov[k][d] * M[r][d];
        double s = (double)g2[r] / sqrt(var + EPS);
        for (int k = 0; k < 3; k++) M[r][k] *= s;
        c[r] = s * (c[r] - mean) + (double)be2[r];
    }
    for (int o = 0; o < 8; o++) {               // conv w3 [8,3]
        for (int k = 0; k < 3; k++) {
            double a = 0.0;
            for (int r = 0; r < 3; r++) a += (double)w3[o * 3 + r] * M[r][k];
            Mn[o][k] = a;
        }
        double a = (double)b3[o];
        for (int r = 0; r < 3; r++) a += (double)w3[o * 3 + r] * c[r];
        cn[o] = a;
    }
    for (int o = 0; o < 8; o++) { for (int k = 0; k < 3; k++) M[o][k] = Mn[o][k]; c[o] = cn[o]; }
    for (int o = 0; o < 8; o++) {               // conv w4 [8,8]
        for (int k = 0; k < 3; k++) {
            double a = 0.0;
            for (int r = 0; r < 8; r++) a += (double)w4[o * 8 + r] * M[r][k];
            Mn[o][k] = a;
        }
        double a = (double)b4[o];
        for (int r = 0; r < 8; r++) a += (double)w4[o * 8 + r] * c[r];
        cn[o] = a;
    }
    for (int o = 0; o < 8; o++) { for (int k = 0; k < 3; k++) M[o][k] = Mn[o][k]; c[o] = cn[o]; }
    for (int o = 0; o < 8; o++) {               // BN5
        double mean = c[o];
        for (int k = 0; k < 3; k++) mean += M[o][k] * m[k];
        double var = 0.0;
        for (int k = 0; k < 3; k++)
            for (int d = 0; d < 3; d++)
                var += M[o][k] * Cov[k][d] * M[o][d];
        double s = (double)g5[o] / sqrt(var + EPS);
        for (int k = 0; k < 3; k++) M[o][k] *= s;
        c[o] = s * (c[o] - mean) + (double)be5[o];
    }
    const float* Ws[3] = { w6, w7, w8 };
    const float* Bs[3] = { b6, b7, b8 };
    for (int L = 0; L < 3; L++) {
        const float* Wl = Ws[L];
        const float* Bl = Bs[L];
        for (int o = 0; o < 8; o++) {
            for (int k = 0; k < 3; k++) {
                double a = 0.0;
                for (int r = 0; r < 8; r++) a += (double)Wl[o * 8 + r] * M[r][k];
                Mn[o][k] = a;
            }
            double a = (double)Bl[o];
            for (int r = 0; r < 8; r++) a += (double)Wl[o * 8 + r] * c[r];
            cn[o] = a;
        }
        for (int o = 0; o < 8; o++) { for (int k = 0; k < 3; k++) M[o][k] = Mn[o][k]; c[o] = cn[o]; }
    }

    for (int o = 0; o < 8; o++) {
        for (int k = 0; k < 3; k++) g_A[o * 3 + k] = (float)M[o][k];
        g_c[o] = (float)c[o];
    }
}

// ---------------------------------------------------------------------------
// Pass 3: out = A x + c.  REVERSED traversal (batch + pixel-chunk) so the
// tail of x — most recently streamed through L2 by reduce — is read first.
// 2 quads per thread for load/store MLP.  Streaming stores keep x in L2.
// ---------------------------------------------------------------------------
__global__ void __launch_bounds__(256) apply_kernel(const float4* __restrict__ X,
                                                    float4* __restrict__ OUT) {
    const int b  = (BB - 1) - blockIdx.y;            // reverse batch
    const int rb = (APL_GX - 1) - blockIdx.x;        // reverse pixel chunk
    const int p0 = rb * 512 + threadIdx.x;           // quad 0
    const int p1 = p0 + 256;                         // quad 1

    float a0[8], a1[8], a2[8], cc[8];
#pragma unroll
    for (int o = 0; o < 8; o++) {
        a0[o] = g_A[o * 3 + 0];
        a1[o] = g_A[o * 3 + 1];
        a2[o] = g_A[o * 3 + 2];
        cc[o] = g_c[o];
    }

    const float4* base = X + (size_t)b * 3 * HW4;
    float4 x0a = __ldg(base + p0);
    float4 x1a = __ldg(base + p0 + HW4);
    float4 x2a = __ldg(base + p0 + 2 * HW4);
    float4 x0b = __ldg(base + p1);
    float4 x1b = __ldg(base + p1 + HW4);
    float4 x2b = __ldg(base + p1 + 2 * HW4);

    float4* ob = OUT + (size_t)b * 8 * HW4;
#pragma unroll
    for (int o = 0; o < 8; o++) {
        float4 r;
        r.x = fmaf(a0[o], x0a.x, fmaf(a1[o], x1a.x, fmaf(a2[o], x2a.x, cc[o])));
        r.y = fmaf(a0[o], x0a.y, fmaf(a1[o], x1a.y, fmaf(a2[o], x2a.y, cc[o])));
        r.z = fmaf(a0[o], x0a.z, fmaf(a1[o], x1a.z, fmaf(a2[o], x2a.z, cc[o])));
        r.w = fmaf(a0[o], x0a.w, fmaf(a1[o], x1a.w, fmaf(a2[o], x2a.w, cc[o])));
        __stcs(ob + o * HW4 + p0, r);
        float4 q;
        q.x = fmaf(a0[o], x0b.x, fmaf(a1[o], x1b.x, fmaf(a2[o], x2b.x, cc[o])));
        q.y = fmaf(a0[o], x0b.y, fmaf(a1[o], x1b.y, fmaf(a2[o], x2b.y, cc[o])));
        q.z = fmaf(a0[o], x0b.z, fmaf(a1[o], x1b.z, fmaf(a2[o], x2b.z, cc[o])));
        q.w = fmaf(a0[o], x0b.w, fmaf(a1[o], x1b.w, fmaf(a2[o], x2b.w, cc[o])));
        __stcs(ob + o * HW4 + p1, q);
    }
}

extern "C" void kernel_launch(void* const* d_in, const int* in_sizes, int n_in,
                              void* d_out, int out_size) {
    const float* x1  = (const float*)d_in[0];
    const float* w1  = (const float*)d_in[1];
    const float* b1  = (const float*)d_in[2];
    const float* g2  = (const float*)d_in[3];
    const float* be2 = (const float*)d_in[4];
    const float* w3  = (const float*)d_in[5];
    const float* b3  = (const float*)d_in[6];
    const float* w4  = (const float*)d_in[7];
    const float* b4  = (const float*)d_in[8];
    const float* g5  = (const float*)d_in[9];
    const float* be5 = (const float*)d_in[10];
    const float* w6  = (const float*)d_in[11];
    const float* b6  = (const float*)d_in[12];
    const float* w7  = (const float*)d_in[13];
    const float* b7  = (const float*)d_in[14];
    const float* w8  = (const float*)d_in[15];
    const float* b8  = (const float*)d_in[16];

    reduce_kernel<<<dim3(RED_GX, BB), RED_THREADS>>>((const float4*)x1);
    finalize_kernel<<<1, 288>>>(w1, b1, g2, be2, w3, b3, w4, b4,
                                g5, be5, w6, b6, w7, b7, w8, b8);
    apply_kernel<<<dim3(APL_GX, BB), 256>>>((const float4*)x1, (float4*)d_out);
}